// round 9
// baseline (speedup 1.0000x reference)
#include <cuda_runtime.h>
#include <cuda_bf16.h>
#include <math.h>

#define N_NODES 100000
#define N_EDGES 1600000
#define HID 128
#define NB_SCAN 98   // ceil(100000/1024)

// ---------------- scratch (device globals; no allocation allowed) ----------------
__device__ float g_h[(size_t)N_NODES * HID];     // h0, then h1 (overwritten in place)
__device__ float g_m[(size_t)N_NODES * HID];     // h @ W_l
__device__ float g_base[(size_t)N_NODES * HID];  // h @ W_r + b
__device__ int   g_deg[N_NODES];
__device__ float g_inv_deg[N_NODES];
__device__ int   g_row_start[N_NODES];
__device__ int   g_cursor[N_NODES];
__device__ int   g_csr_src[N_EDGES];
__device__ int   g_blocksums[NB_SCAN];

// ---------------- CSR build ----------------
__global__ void k_zero_deg() {
    int i = blockIdx.x * blockDim.x + threadIdx.x;
    if (i < N_NODES) g_deg[i] = 0;
}

__global__ void k_deg(const int* __restrict__ edge) {
    int e = blockIdx.x * blockDim.x + threadIdx.x;
    if (e < N_EDGES) {
        int dst = edge[N_EDGES + e];
        atomicAdd(&g_deg[dst], 1);
    }
}

__global__ void k_scan1() {
    __shared__ int s[1024];
    int tid = threadIdx.x;
    int i = blockIdx.x * 1024 + tid;
    int v = (i < N_NODES) ? g_deg[i] : 0;
    s[tid] = v;
    __syncthreads();
    for (int off = 1; off < 1024; off <<= 1) {
        int t = (tid >= off) ? s[tid - off] : 0;
        __syncthreads();
        s[tid] += t;
        __syncthreads();
    }
    int incl = s[tid];
    if (i < N_NODES) g_row_start[i] = incl - v;  // exclusive within block
    if (tid == 1023) g_blocksums[blockIdx.x] = incl;
}

__global__ void k_scan2() {
    if (threadIdx.x == 0) {
        int run = 0;
        for (int b = 0; b < NB_SCAN; b++) {
            int t = g_blocksums[b];
            g_blocksums[b] = run;
            run += t;
        }
    }
}

__global__ void k_scan3() {
    int i = blockIdx.x * 1024 + threadIdx.x;
    if (i < N_NODES) {
        int rs = g_row_start[i] + g_blocksums[i >> 10];
        g_row_start[i] = rs;
        g_cursor[i] = rs;
        int d = g_deg[i];
        g_inv_deg[i] = 1.0f / fmaxf((float)d, 1.0f);
    }
}

__global__ void k_fill(const int* __restrict__ edge) {
    int e = blockIdx.x * blockDim.x + threadIdx.x;
    if (e < N_EDGES) {
        int src = edge[e];
        int dst = edge[N_EDGES + e];
        int pos = atomicAdd(&g_cursor[dst], 1);
        g_csr_src[pos] = src;
    }
}

// ---------------- feature build: h0 = concat(x, user_emb, loc_emb, time_emb) ----------------
__global__ void k_feat(const float* __restrict__ x,
                       const int* __restrict__ user_ids,
                       const int* __restrict__ locations,
                       const float* __restrict__ time_features,
                       const float* __restrict__ user_emb,
                       const float* __restrict__ loc_emb,
                       const float* __restrict__ W_time,
                       const float* __restrict__ b_time) {
    int warp = threadIdx.x >> 5;
    int lane = threadIdx.x & 31;
    int node = blockIdx.x * 8 + warp;
    if (node >= N_NODES) return;

    float4 v;
    if (lane < 16) {
        v = ((const float4*)(x + (size_t)node * 64))[lane];
    } else if (lane < 24) {
        int uid = user_ids[node];
        v = ((const float4*)(user_emb + (size_t)uid * 32))[lane - 16];
    } else if (lane < 28) {
        int loc = locations[node];
        v = ((const float4*)(loc_emb + (size_t)loc * 16))[lane - 24];
    } else {
        int c0 = (lane - 28) * 4;
        float t0 = time_features[node * 4 + 0];
        float t1 = time_features[node * 4 + 1];
        float t2 = time_features[node * 4 + 2];
        float t3 = time_features[node * 4 + 3];
        float r[4];
#pragma unroll
        for (int j = 0; j < 4; j++) {
            int c = c0 + j;
            r[j] = b_time[c] + t0 * W_time[0 * 16 + c] + t1 * W_time[1 * 16 + c]
                 + t2 * W_time[2 * 16 + c] + t3 * W_time[3 * 16 + c];
        }
        v = make_float4(r[0], r[1], r[2], r[3]);
    }
    ((float4*)(g_h + (size_t)node * HID))[lane] = v;
}

// ---------------- dual GEMM: g_m = h @ W_l ; g_base = h @ W_r + b ----------------
// 512 threads / 16 warps; 4 rows per warp; 64-row tile in 32KB static smem.
// W read via __ldg float4 (L1-resident, uniform across warps). Plain FFMA.
__global__ __launch_bounds__(512)
void k_dual_gemm(const float* __restrict__ Wl,
                 const float* __restrict__ Wr,
                 const float* __restrict__ bias) {
    __shared__ float sA[64 * 128];  // 32 KB

    int warp = threadIdx.x >> 5;
    int lane = threadIdx.x & 31;
    int r0 = warp * 4;

    const float4* Wl4 = (const float4*)Wl;  // [k*32+lane] = cols 4lane..4lane+3 of row k
    const float4* Wr4 = (const float4*)Wr;

    float4 bv = ((const float4*)bias)[lane];

    const int numTiles = (N_NODES + 63) / 64;
    for (int tile = blockIdx.x; tile < numTiles; tile += gridDim.x) {
        int row0 = tile * 64;
        __syncthreads();  // retire previous iteration's readers of sA
        {
            const float4* srcA = (const float4*)(g_h + (size_t)row0 * HID);
            float4* dA = (float4*)sA;
            for (int i = threadIdx.x; i < 64 * 32; i += 512) {
                int r = i >> 5;
                dA[i] = (row0 + r < N_NODES) ? srcA[i] : make_float4(0.f, 0.f, 0.f, 0.f);
            }
        }
        __syncthreads();

        float4 accM[4], accB[4];
#pragma unroll
        for (int r = 0; r < 4; r++) {
            accM[r] = make_float4(0.f, 0.f, 0.f, 0.f);
            accB[r] = bv;
        }

#pragma unroll 4
        for (int k = 0; k < 128; k++) {
            float4 wl = __ldg(&Wl4[k * 32 + lane]);
            float4 wr = __ldg(&Wr4[k * 32 + lane]);
#pragma unroll
            for (int r = 0; r < 4; r++) {
                float a = sA[(r0 + r) * 128 + k];
                accM[r].x = fmaf(a, wl.x, accM[r].x);
                accM[r].y = fmaf(a, wl.y, accM[r].y);
                accM[r].z = fmaf(a, wl.z, accM[r].z);
                accM[r].w = fmaf(a, wl.w, accM[r].w);
                accB[r].x = fmaf(a, wr.x, accB[r].x);
                accB[r].y = fmaf(a, wr.y, accB[r].y);
                accB[r].z = fmaf(a, wr.z, accB[r].z);
                accB[r].w = fmaf(a, wr.w, accB[r].w);
            }
        }

#pragma unroll
        for (int r = 0; r < 4; r++) {
            int row = row0 + r0 + r;
            if (row < N_NODES) {
                ((float4*)(g_m + (size_t)row * HID))[lane] = accM[r];
                ((float4*)(g_base + (size_t)row * HID))[lane] = accB[r];
            }
        }
    }
}

// ---------------- aggregation + finish (+ optional fused classifier) ----------------
// one warp per node; lane l owns columns [4l, 4l+4)
template <bool FINAL>
__global__ void k_aggfin(const float* __restrict__ Wc,
                         const float* __restrict__ bc,
                         float* __restrict__ out) {
    int warp = threadIdx.x >> 5;
    int lane = threadIdx.x & 31;
    int node = blockIdx.x * 8 + warp;
    if (node >= N_NODES) return;

    int start = g_row_start[node];
    int d = g_deg[node];
    const float4* mp = (const float4*)g_m;

    float4 acc = make_float4(0.f, 0.f, 0.f, 0.f);
    int e = 0;
    for (; e + 4 <= d; e += 4) {
        int i0 = g_csr_src[start + e + 0];
        int i1 = g_csr_src[start + e + 1];
        int i2 = g_csr_src[start + e + 2];
        int i3 = g_csr_src[start + e + 3];
        float4 v0 = mp[(size_t)i0 * 32 + lane];
        float4 v1 = mp[(size_t)i1 * 32 + lane];
        float4 v2 = mp[(size_t)i2 * 32 + lane];
        float4 v3 = mp[(size_t)i3 * 32 + lane];
        acc.x += (v0.x + v1.x) + (v2.x + v3.x);
        acc.y += (v0.y + v1.y) + (v2.y + v3.y);
        acc.z += (v0.z + v1.z) + (v2.z + v3.z);
        acc.w += (v0.w + v1.w) + (v2.w + v3.w);
    }
    for (; e < d; e++) {
        int i0 = g_csr_src[start + e];
        float4 v0 = mp[(size_t)i0 * 32 + lane];
        acc.x += v0.x; acc.y += v0.y; acc.z += v0.z; acc.w += v0.w;
    }

    float inv = g_inv_deg[node];
    float4 b = ((const float4*)(g_base + (size_t)node * HID))[lane];
    float4 hv;
    hv.x = fmaxf(b.x + acc.x * inv, 0.f);
    hv.y = fmaxf(b.y + acc.y * inv, 0.f);
    hv.z = fmaxf(b.z + acc.z * inv, 0.f);
    hv.w = fmaxf(b.w + acc.w * inv, 0.f);

    if (!FINAL) {
        ((float4*)(g_h + (size_t)node * HID))[lane] = hv;
    } else {
        float p = hv.x * Wc[4 * lane + 0] + hv.y * Wc[4 * lane + 1]
                + hv.z * Wc[4 * lane + 2] + hv.w * Wc[4 * lane + 3];
#pragma unroll
        for (int o = 16; o > 0; o >>= 1) p += __shfl_xor_sync(0xffffffffu, p, o);
        if (lane == 0) {
            float z = p + bc[0];
            out[node] = 1.0f / (1.0f + expf(-z));
        }
    }
}

// ---------------- launch: kernel launches ONLY (graph-capturable) ----------------
extern "C" void kernel_launch(void* const* d_in, const int* in_sizes, int n_in,
                              void* d_out, int out_size) {
    const float* x         = (const float*)d_in[0];
    const int*   edge      = (const int*)d_in[1];
    const int*   user_ids  = (const int*)d_in[2];
    const int*   locations = (const int*)d_in[3];
    const float* time_feat = (const float*)d_in[4];
    const float* user_emb  = (const float*)d_in[5];
    const float* loc_emb   = (const float*)d_in[6];
    const float* W_time    = (const float*)d_in[7];
    const float* b_time    = (const float*)d_in[8];
    const float* W1_l      = (const float*)d_in[9];
    const float* b1        = (const float*)d_in[10];
    const float* W1_r      = (const float*)d_in[11];
    const float* W2_l      = (const float*)d_in[12];
    const float* b2        = (const float*)d_in[13];
    const float* W2_r      = (const float*)d_in[14];
    const float* Wc        = (const float*)d_in[15];
    const float* bc        = (const float*)d_in[16];
    float* out = (float*)d_out;

    // --- CSR build ---
    k_zero_deg<<<(N_NODES + 255) / 256, 256>>>();
    k_deg<<<(N_EDGES + 255) / 256, 256>>>(edge);
    k_scan1<<<NB_SCAN, 1024>>>();
    k_scan2<<<1, 32>>>();
    k_scan3<<<NB_SCAN, 1024>>>();
    k_fill<<<(N_EDGES + 255) / 256, 256>>>(edge);

    // --- features ---
    k_feat<<<(N_NODES + 7) / 8, 256>>>(x, user_ids, locations, time_feat,
                                       user_emb, loc_emb, W_time, b_time);

    // --- layer 1 ---
    k_dual_gemm<<<148, 512>>>(W1_l, W1_r, b1);
    k_aggfin<false><<<(N_NODES + 7) / 8, 256>>>(Wc, bc, out);

    // --- layer 2 + classifier ---
    k_dual_gemm<<<148, 512>>>(W2_l, W2_r, b2);
    k_aggfin<true><<<(N_NODES + 7) / 8, 256>>>(Wc, bc, out);
}